// round 13
// baseline (speedup 1.0000x reference)
#include <cuda_runtime.h>
#include <cstdint>

// GRU: B=64, T=2048, I=256, H=256.  out = concat(out[B,T,H], hN[B,H]) fp32.
//
// 16 clusters x 8 CTAs (128 SMs). Cluster owns 4 batches; CTA rank owns
// j in [32r,32r+32) => fused rows {j,256+j,512+j} (96 rows x 512 fused K).
// 512 threads: thread (jj,kc) owns ALL 3 gate rows of its j, fused-K chunk
// [32kc,32kc+32) in registers (3 x 32 = 96 floats). 16 warps -> 4/SMSP.
// Each A float4 load feeds 6 fma2 (3 gates x 2). Per-warp LDS requests have
// 16 distinct addresses (kc) x2 dup (jj) -> 2 wavefronts per LDS.128.
// accS banks: 2*kc + 5*(32g+jj) + b -> injective per warp phase.

static constexpr int B_  = 64;
static constexpr int T_  = 2048;
static constexpr int I_  = 256;
static constexpr int H_  = 256;

static constexpr int CL      = 8;
static constexpr int NB      = 4;
static constexpr int NCL     = 16;
static constexpr int THREADS = 512;   // 32 j x 16 k-chunks
static constexpr int CHS     = 36;    // A chunk stride (32 + 4 pad)
static constexpr int APB     = 16 * CHS;     // 576 floats per batch
static constexpr int APP     = NB * APB;     // 2304 per parity
static constexpr int ARS     = 5;            // acc row stride
static constexpr int ASLAB   = 96 * ARS + 2; // 482 (mod 32 = 2)

typedef unsigned long long u64;

__device__ __forceinline__ void fma2(u64 &acc, u64 a, u64 b) {
    asm("fma.rn.f32x2 %0, %1, %2, %0;" : "+l"(acc) : "l"(a), "l"(b));
}
__device__ __forceinline__ float sum2(u64 v) {
    float lo, hi;
    asm("mov.b64 {%0,%1}, %2;" : "=f"(lo), "=f"(hi) : "l"(v));
    return lo + hi;
}
__device__ __forceinline__ uint32_t smem_u32(const void* p) {
    return (uint32_t)__cvta_generic_to_shared(p);
}
__device__ __forceinline__ void st_remote_f32(uint32_t laddr, int rank, float v) {
    uint32_t raddr;
    asm("mapa.shared::cluster.u32 %0, %1, %2;" : "=r"(raddr) : "r"(laddr), "r"(rank));
    asm volatile("st.shared::cluster.f32 [%0], %1;" :: "r"(raddr), "f"(v));
}
__device__ __forceinline__ void cluster_arrive_() {
    asm volatile("barrier.cluster.arrive.aligned;" ::: "memory");
}
__device__ __forceinline__ void cluster_wait_() {
    asm volatile("barrier.cluster.wait.aligned;" ::: "memory");
}
__device__ __forceinline__ uint32_t ctarank_() {
    uint32_t r;
    asm("mov.u32 %0, %%cluster_ctarank;" : "=r"(r));
    return r;
}
__device__ __forceinline__ float sigmoidf_(float x) {
    return 1.0f / (1.0f + __expf(-x));
}
__device__ __forceinline__ float tanhf_fast_(float x) {
    return 1.0f - 2.0f / (1.0f + __expf(2.0f * x));
}

__global__ void __launch_bounds__(THREADS, 1) __cluster_dims__(CL, 1, 1)
gru_persistent_kernel(const float* __restrict__ x,
                      const float* __restrict__ h0,
                      const float* __restrict__ Wih,
                      const float* __restrict__ bih,
                      const float* __restrict__ Whh,
                      const float* __restrict__ bhh,
                      float* __restrict__ out,
                      int out_size)
{
    __shared__ float Ap[2 * APP];        // [parity][b][16 chunks][36]; ch<8: h, ch>=8: x
    __shared__ float accS[16 * ASLAB];   // [kc slab 482][row*5 + b]
    __shared__ float bias[4 * 32];       // r-comb, hc, ic, u-comb

    const int tid  = threadIdx.x;
    const int rank = (int)ctarank_();
    const int b0   = (blockIdx.x >> 3) * NB;

    const int kc = tid & 15;             // k-chunk 0..15 (lane-varying)
    const int jj = tid >> 4;             // j within slice, 0..31

    // ---- weights in registers: 3 gate rows x 32-float chunk = 96 floats
    ulonglong2 w0[8], w1[8], w2[8];
    {
        const float* base = (kc < 8) ? Whh : Wih;
        const int colb = (kc & 7) << 5;
        const int jg = (rank << 5) + jj;
        const float* s0 = base + (size_t)(jg)       * 256 + colb;
        const float* s1 = base + (size_t)(256 + jg) * 256 + colb;
        const float* s2 = base + (size_t)(512 + jg) * 256 + colb;
        #pragma unroll
        for (int k4 = 0; k4 < 8; ++k4) {
            w0[k4] = *(const ulonglong2*)(s0 + (k4 << 2));
            w1[k4] = *(const ulonglong2*)(s1 + (k4 << 2));
            w2[k4] = *(const ulonglong2*)(s2 + (k4 << 2));
        }
    }

    // ---- combined biases
    if (tid < 32) {
        int jg = (rank << 5) + tid;
        bias[tid]      = bhh[jg]       + bih[jg];
        bias[32 + tid] = bhh[256 + jg];
        bias[64 + tid] = bih[256 + jg];
        bias[96 + tid] = bhh[512 + jg] + bih[512 + jg];
    }

    // ---- h0 + x(0) into Ap[0] (chunked layout, 32-float chunks)
    for (int i4 = tid; i4 < NB * 64; i4 += THREADS) {
        int b = i4 >> 6, kk = i4 & 63;
        int ch = kk >> 3, pos = (kk & 7) << 2;
        *(float4*)(Ap + b * APB + ch * CHS + pos) =
            *(const float4*)(h0 + (size_t)(b0 + b) * H_ + (kk << 2));
        *(float4*)(Ap + b * APB + (8 + ch) * CHS + pos) =
            *(const float4*)(x + ((size_t)(b0 + b) * T_) * I_ + (kk << 2));
    }

    // ---- cp.async x(1) -> Ap[1].x
    const uint32_t ap_u32 = smem_u32(Ap);
    if (tid < NB * 64) {
        int b = tid >> 6, kk = tid & 63;
        int ch = 8 + (kk >> 3), pos = (kk & 7) << 2;
        const float* gsrc = x + ((size_t)(b0 + b) * T_ + 1) * I_ + (kk << 2);
        uint32_t s = ap_u32 + (uint32_t)((APP + b * APB + ch * CHS + pos) * 4);
        asm volatile("cp.async.ca.shared.global [%0], [%1], 16;" :: "r"(s), "l"(gsrc));
    }
    asm volatile("cp.async.commit_group;");

    cluster_arrive_();
    cluster_wait_();

    const int eb  = tid >> 5;            // elementwise batch (tid<128)
    const int ej  = tid & 31;
    const int ejg = (rank << 5) + ej;
    const size_t BTH = (size_t)B_ * T_ * H_;

    for (int t = 0; t < T_; ++t) {
        const int p  = t & 1;
        const int pn = p ^ 1;

        // ---- 1. fused GEMM: 3 gate rows x 4 batches over 32-K chunk,
        //         one batch at a time (low live registers, no spill)
        {
            const float* A = Ap + p * APP + kc * CHS;
            float* dst = accS + kc * ASLAB + jj * ARS;
            #pragma unroll 1
            for (int b = 0; b < NB; ++b) {
                const float* Ab = A + b * APB;
                u64 c0 = 0, c1 = 0, c2 = 0;
                #pragma unroll
                for (int k4 = 0; k4 < 8; ++k4) {
                    ulonglong2 v = *(const ulonglong2*)(Ab + (k4 << 2));
                    fma2(c0, v.x, w0[k4].x); fma2(c0, v.y, w0[k4].y);
                    fma2(c1, v.x, w1[k4].x); fma2(c1, v.y, w1[k4].y);
                    fma2(c2, v.x, w2[k4].x); fma2(c2, v.y, w2[k4].y);
                }
                dst[b]                = sum2(c0);   // gate r rows  [0,32)
                dst[32 * ARS + b]     = sum2(c1);   // gate c rows  [32,64)
                dst[64 * ARS + b]     = sum2(c2);   // gate u rows  [64,96)
            }
        }
        __syncthreads();

        // ---- 2a. elementwise GRU + out + DSMEM h-broadcast (threads 0..127)
        if (tid < 128) {
            const int b = eb, j = ej;
            float rsum = bias[j], usum = bias[96 + j];
            float hc = bias[32 + j], ic = bias[64 + j];
            #pragma unroll
            for (int q = 0; q < 16; ++q) {
                const float* s = accS + q * ASLAB;
                rsum += s[j * ARS + b];
                usum += s[(64 + j) * ARS + b];
                float c = s[(32 + j) * ARS + b];
                if (q < 8) hc += c; else ic += c;
            }
            float rgt = sigmoidf_(rsum);
            float u   = sigmoidf_(usum);
            float n   = tanhf_fast_(ic + rgt * hc);

            const int hoff = b * APB + (ejg >> 5) * CHS + (ejg & 31);
            float hold = Ap[p * APP + hoff];
            float hy   = hold + u * (n - hold);

            out[((size_t)(b0 + b) * T_ + t) * H_ + ejg] = hy;

            uint32_t laddr = ap_u32 + (uint32_t)((pn * APP + hoff) * 4);
            #pragma unroll
            for (int pr = 0; pr < CL; ++pr)
                st_remote_f32(laddr, pr, hy);
        }
        // ---- 2b. x(t+2) prefetch into Ap[p].x (threads 128..383)
        else if (t + 2 < T_ && tid < 128 + NB * 64) {
            int i4 = tid - 128;
            int b = i4 >> 6, kk = i4 & 63;
            int ch = 8 + (kk >> 3), pos = (kk & 7) << 2;
            const float* gsrc = x + ((size_t)(b0 + b) * T_ + (t + 2)) * I_ + (kk << 2);
            uint32_t s = ap_u32 + (uint32_t)((p * APP + b * APB + ch * CHS + pos) * 4);
            asm volatile("cp.async.ca.shared.global [%0], [%1], 16;" :: "r"(s), "l"(gsrc));
        }
        asm volatile("cp.async.commit_group;");
        asm volatile("cp.async.wait_group 1;" ::: "memory");  // x(t+1) landed

        // ---- 3. cluster barrier: releases h-broadcasts, acquires peers'
        cluster_arrive_();
        cluster_wait_();
    }

    // ---- final hidden state: h(T) in parity 0 (T even)
    if (out_size >= (int)(BTH + (size_t)B_ * H_)) {
        for (int i = tid; i < NB * H_; i += THREADS) {
            int b = i >> 8, j = i & 255;
            out[BTH + (size_t)(b0 + b) * H_ + j] =
                Ap[b * APB + (j >> 5) * CHS + (j & 31)];
        }
    }
}

extern "C" void kernel_launch(void* const* d_in, const int* in_sizes, int n_in,
                              void* d_out, int out_size) {
    const float* x    = (const float*)d_in[0];
    const float* h0   = (const float*)d_in[1];
    const float* Wih  = (const float*)d_in[2];
    const float* bih  = (const float*)d_in[3];
    const float* Whh  = (const float*)d_in[4];
    const float* bhh  = (const float*)d_in[5];
    float* out = (float*)d_out;

    gru_persistent_kernel<<<NCL * CL, THREADS>>>(
        x, h0, Wih, bih, Whh, bhh, out, out_size);
}